// round 3
// baseline (speedup 1.0000x reference)
#include <cuda_runtime.h>
#include <math.h>

// ---------------- problem constants ----------------
#define S 2048
#define HID 2048
#define NH 32
#define HD 64
#define Q_W 4096            // 2*HID
#define SCALE 0.125f        // 1/sqrt(64)
#define LAM_INIT 0.7836057665316245
#define NEG_BIG (-1e30f)

// ---------------- scratch (device globals, no allocation) ----------------
__device__ float g_Q[(size_t)S * Q_W];
__device__ float g_K[(size_t)S * Q_W];
__device__ float g_V[(size_t)S * HID];
__device__ float g_O1[(size_t)S * HID];
__device__ float g_O2[(size_t)S * HID];
__device__ float g_CTX[(size_t)S * HID];
__device__ float g_cos[S * 32];
__device__ float g_sin[S * 32];
__device__ float g_lam;

// ---------------- lambda scalar ----------------
__global__ void lam_kernel(const float* __restrict__ lq1, const float* __restrict__ lk1,
                           const float* __restrict__ lq2, const float* __restrict__ lk2) {
    if (threadIdx.x == 0) {
        float d1 = 0.f, d2 = 0.f;
        for (int i = 0; i < HD; i++) { d1 += lq1[i] * lk1[i]; d2 += lq2[i] * lk2[i]; }
        g_lam = expf(d1) - expf(d2) + (float)LAM_INIT;
    }
}

// ---------------- RoPE cos/sin table (float64 like reference) ----------------
__global__ void rope_table_kernel() {
    int idx = blockIdx.x * blockDim.x + threadIdx.x;
    if (idx >= S * 32) return;
    int s = idx >> 5;
    int d = idx & 31;
    double inv = pow(10000.0, -(double)d / 32.0);
    double ang = (double)s * inv;
    g_cos[idx] = (float)cos(ang);
    g_sin[idx] = (float)sin(ang);
}

// ---------------- RoPE in-place on [S, 4096] (both q1|q2 halves) ----------------
__global__ void rope_apply_kernel(float* __restrict__ X) {
    int idx = blockIdx.x * blockDim.x + threadIdx.x;   // S*2048 pairs
    if (idx >= S * 2048) return;
    int s    = idx >> 11;
    int p    = idx & 2047;
    int half = p >> 10;
    int rem  = p & 1023;
    int h    = rem >> 5;
    int d    = rem & 31;
    size_t base = (size_t)s * Q_W + half * HID + h * HD + d;
    float x1 = X[base];
    float x2 = X[base + 32];
    float c  = g_cos[s * 32 + d];
    float sn = g_sin[s * 32 + d];
    X[base]      = x1 * c - x2 * sn;   // d < 32: rot = -x[d+32]
    X[base + 32] = x2 * c + x1 * sn;   // d >= 32: rot = x[d-32]
}

// ---------------- SGEMM: C[M,N] = A[M,K] @ B[N,K]^T  (both row-major) ------
// 128x128 block tile, BK=16, 256 threads, 8x8 per thread.
__global__ __launch_bounds__(256, 2)
void sgemm_nt(const float* __restrict__ A, const float* __restrict__ B,
              float* __restrict__ C, int M, int N, int K) {
    __shared__ float As[16][128];
    __shared__ float Bs[16][128];

    int tid  = threadIdx.x;
    int bm   = blockIdx.y * 128;
    int bn   = blockIdx.x * 128;
    int trow = (tid >> 4) << 3;    // 0..120 step 8
    int tcol = (tid & 15) << 3;

    int lr  = tid >> 2;            // 0..63
    int lc4 = (tid & 3) << 2;      // 0,4,8,12

    float acc[8][8];
#pragma unroll
    for (int i = 0; i < 8; i++)
#pragma unroll
        for (int j = 0; j < 8; j++) acc[i][j] = 0.f;

    const float* Ap0 = A + (size_t)(bm + lr) * K + lc4;
    const float* Ap1 = A + (size_t)(bm + lr + 64) * K + lc4;
    const float* Bp0 = B + (size_t)(bn + lr) * K + lc4;
    const float* Bp1 = B + (size_t)(bn + lr + 64) * K + lc4;

    for (int k0 = 0; k0 < K; k0 += 16) {
        float4 a0 = *(const float4*)(Ap0 + k0);
        float4 a1 = *(const float4*)(Ap1 + k0);
        float4 b0 = *(const float4*)(Bp0 + k0);
        float4 b1 = *(const float4*)(Bp1 + k0);
        __syncthreads();
        As[lc4 + 0][lr] = a0.x; As[lc4 + 1][lr] = a0.y;
        As[lc4 + 2][lr] = a0.z; As[lc4 + 3][lr] = a0.w;
        As[lc4 + 0][lr + 64] = a1.x; As[lc4 + 1][lr + 64] = a1.y;
        As[lc4 + 2][lr + 64] = a1.z; As[lc4 + 3][lr + 64] = a1.w;
        Bs[lc4 + 0][lr] = b0.x; Bs[lc4 + 1][lr] = b0.y;
        Bs[lc4 + 2][lr] = b0.z; Bs[lc4 + 3][lr] = b0.w;
        Bs[lc4 + 0][lr + 64] = b1.x; Bs[lc4 + 1][lr + 64] = b1.y;
        Bs[lc4 + 2][lr + 64] = b1.z; Bs[lc4 + 3][lr + 64] = b1.w;
        __syncthreads();
#pragma unroll
        for (int k = 0; k < 16; k++) {
            float4 aA = *(const float4*)&As[k][trow];
            float4 aB = *(const float4*)&As[k][trow + 4];
            float4 bA = *(const float4*)&Bs[k][tcol];
            float4 bB = *(const float4*)&Bs[k][tcol + 4];
            float a[8] = {aA.x, aA.y, aA.z, aA.w, aB.x, aB.y, aB.z, aB.w};
            float b[8] = {bA.x, bA.y, bA.z, bA.w, bB.x, bB.y, bB.z, bB.w};
#pragma unroll
            for (int i = 0; i < 8; i++)
#pragma unroll
                for (int j = 0; j < 8; j++)
                    acc[i][j] += a[i] * b[j];
        }
    }

#pragma unroll
    for (int i = 0; i < 8; i++) {
        float4 c0 = make_float4(acc[i][0], acc[i][1], acc[i][2], acc[i][3]);
        float4 c1 = make_float4(acc[i][4], acc[i][5], acc[i][6], acc[i][7]);
        float* row = C + (size_t)(bm + trow + i) * N + bn + tcol;
        *(float4*)(row)     = c0;
        *(float4*)(row + 4) = c1;
    }
}

// ---------------- Flash attention (one stream, causal) ----------------
// grid: (S/64 q-tiles, NH heads). 256 threads. Tiles 64x64, D=64.
// Output: O[s*HID + h*64 + d] = softmax(Q K^T * scale + causal) @ V   (normalized)
#define PS_STRIDE 68
__global__ __launch_bounds__(256, 2)
void flash_attn_kernel(const float* __restrict__ Qg, const float* __restrict__ Kg,
                       const float* __restrict__ Vg, float* __restrict__ Og,
                       int col_off) {
    extern __shared__ float sm[];
    float* Qs = sm;                 // [64][64]  d-major: Qs[d*64 + row]
    float* Ks = Qs + 64 * 64;       // [64][64]  d-major: Ks[d*64 + col]
    float* Vs = Ks + 64 * 64;       // [64][64]  kv-major: Vs[kv*64 + d]
    float* Ps = Vs + 64 * 64;       // [64][PS_STRIDE]

    int tid = threadIdx.x;
    int qt  = blockIdx.x;
    int h   = blockIdx.y;
    int rg  = tid >> 4;             // 0..15 (row group, 4 rows each)
    int cg  = tid & 15;             // 0..15 (col group, 4 cols each)
    int r0  = qt * 64;

    int lrow = tid >> 2;            // 0..63
    int ldb  = (tid & 3) << 4;      // 0,16,32,48

    // load Q tile (transposed into Qs)
    {
        const float* qp = Qg + (size_t)(r0 + lrow) * Q_W + col_off + h * HD + ldb;
        float4 q0 = *(const float4*)(qp);
        float4 q1 = *(const float4*)(qp + 4);
        float4 q2 = *(const float4*)(qp + 8);
        float4 q3 = *(const float4*)(qp + 12);
        Qs[(ldb + 0) * 64 + lrow] = q0.x; Qs[(ldb + 1) * 64 + lrow] = q0.y;
        Qs[(ldb + 2) * 64 + lrow] = q0.z; Qs[(ldb + 3) * 64 + lrow] = q0.w;
        Qs[(ldb + 4) * 64 + lrow] = q1.x; Qs[(ldb + 5) * 64 + lrow] = q1.y;
        Qs[(ldb + 6) * 64 + lrow] = q1.z; Qs[(ldb + 7) * 64 + lrow] = q1.w;
        Qs[(ldb + 8) * 64 + lrow] = q2.x; Qs[(ldb + 9) * 64 + lrow] = q2.y;
        Qs[(ldb + 10) * 64 + lrow] = q2.z; Qs[(ldb + 11) * 64 + lrow] = q2.w;
        Qs[(ldb + 12) * 64 + lrow] = q3.x; Qs[(ldb + 13) * 64 + lrow] = q3.y;
        Qs[(ldb + 14) * 64 + lrow] = q3.z; Qs[(ldb + 15) * 64 + lrow] = q3.w;
    }

    float m[4], l[4], oacc[4][4];
#pragma unroll
    for (int i = 0; i < 4; i++) {
        m[i] = NEG_BIG; l[i] = 0.f;
#pragma unroll
        for (int j = 0; j < 4; j++) oacc[i][j] = 0.f;
    }

    for (int jt = 0; jt <= qt; jt++) {
        int c0 = jt * 64;
        // load K (transposed) and V (natural)
        {
            const float* kp = Kg + (size_t)(c0 + lrow) * Q_W + col_off + h * HD + ldb;
            float4 k0 = *(const float4*)(kp);
            float4 k1 = *(const float4*)(kp + 4);
            float4 k2 = *(const float4*)(kp + 8);
            float4 k3 = *(const float4*)(kp + 12);
            const float* vp = Vg + (size_t)(c0 + lrow) * HID + h * HD + ldb;
            float4 v0 = *(const float4*)(vp);
            float4 v1 = *(const float4*)(vp + 4);
            float4 v2 = *(const float4*)(vp + 8);
            float4 v3 = *(const float4*)(vp + 12);
            __syncthreads();   // previous tile's PV reads done
            Ks[(ldb + 0) * 64 + lrow] = k0.x; Ks[(ldb + 1) * 64 + lrow] = k0.y;
            Ks[(ldb + 2) * 64 + lrow] = k0.z; Ks[(ldb + 3) * 64 + lrow] = k0.w;
            Ks[(ldb + 4) * 64 + lrow] = k1.x; Ks[(ldb + 5) * 64 + lrow] = k1.y;
            Ks[(ldb + 6) * 64 + lrow] = k1.z; Ks[(ldb + 7) * 64 + lrow] = k1.w;
            Ks[(ldb + 8) * 64 + lrow] = k2.x; Ks[(ldb + 9) * 64 + lrow] = k2.y;
            Ks[(ldb + 10) * 64 + lrow] = k2.z; Ks[(ldb + 11) * 64 + lrow] = k2.w;
            Ks[(ldb + 12) * 64 + lrow] = k3.x; Ks[(ldb + 13) * 64 + lrow] = k3.y;
            Ks[(ldb + 14) * 64 + lrow] = k3.z; Ks[(ldb + 15) * 64 + lrow] = k3.w;
            *(float4*)&Vs[lrow * 64 + ldb]      = v0;
            *(float4*)&Vs[lrow * 64 + ldb + 4]  = v1;
            *(float4*)&Vs[lrow * 64 + ldb + 8]  = v2;
            *(float4*)&Vs[lrow * 64 + ldb + 12] = v3;
            __syncthreads();
        }

        // S = Q @ K^T (frag 4x4)
        float sv[4][4];
#pragma unroll
        for (int i = 0; i < 4; i++)
#pragma unroll
            for (int j = 0; j < 4; j++) sv[i][j] = 0.f;

#pragma unroll 8
        for (int d = 0; d < 64; d++) {
            float4 a = *(const float4*)&Qs[d * 64 + (rg << 2)];
            float4 b = *(const float4*)&Ks[d * 64 + (cg << 2)];
            float av[4] = {a.x, a.y, a.z, a.w};
            float bv[4] = {b.x, b.y, b.z, b.w};
#pragma unroll
            for (int i = 0; i < 4; i++)
#pragma unroll
                for (int j = 0; j < 4; j++) sv[i][j] += av[i] * bv[j];
        }

        bool diag = (jt == qt);
#pragma unroll
        for (int i = 0; i < 4; i++) {
            int grow = r0 + (rg << 2) + i;
#pragma unroll
            for (int j = 0; j < 4; j++) {
                int gcol = c0 + (cg << 2) + j;
                float v = sv[i][j] * SCALE;
                if (diag && gcol > grow) v = NEG_BIG;
                sv[i][j] = v;
            }
        }

        // online softmax per row (reduce across 16 lanes sharing a row group)
#pragma unroll
        for (int i = 0; i < 4; i++) {
            float rmax = fmaxf(fmaxf(sv[i][0], sv[i][1]), fmaxf(sv[i][2], sv[i][3]));
#pragma unroll
            for (int o = 1; o < 16; o <<= 1)
                rmax = fmaxf(rmax, __shfl_xor_sync(0xffffffffu, rmax, o));
            float m_new = fmaxf(m[i], rmax);
            float corr  = expf(m[i] - m_new);
            float ps = 0.f;
#pragma unroll
            for (int j = 0; j < 4; j++) {
                float p = expf(sv[i][j] - m_new);
                sv[i][j] = p;
                ps += p;
            }
#pragma unroll
            for (int o = 1; o < 16; o <<= 1)
                ps += __shfl_xor_sync(0xffffffffu, ps, o);
            l[i] = l[i] * corr + ps;
            m[i] = m_new;
#pragma unroll
            for (int j = 0; j < 4; j++) oacc[i][j] *= corr;
        }

        // write P to smem
#pragma unroll
        for (int i = 0; i < 4; i++) {
            *(float4*)&Ps[((rg << 2) + i) * PS_STRIDE + (cg << 2)] =
                make_float4(sv[i][0], sv[i][1], sv[i][2], sv[i][3]);
        }
        __syncthreads();

        // O += P @ V
#pragma unroll 8
        for (int kv = 0; kv < 64; kv++) {
            float a0 = Ps[((rg << 2) + 0) * PS_STRIDE + kv];
            float a1 = Ps[((rg << 2) + 1) * PS_STRIDE + kv];
            float a2 = Ps[((rg << 2) + 2) * PS_STRIDE + kv];
            float a3 = Ps[((rg << 2) + 3) * PS_STRIDE + kv];
            float4 b = *(const float4*)&Vs[kv * 64 + (cg << 2)];
            float bv[4] = {b.x, b.y, b.z, b.w};
#pragma unroll
            for (int j = 0; j < 4; j++) {
                oacc[0][j] += a0 * bv[j];
                oacc[1][j] += a1 * bv[j];
                oacc[2][j] += a2 * bv[j];
                oacc[3][j] += a3 * bv[j];
            }
        }
        // next-iter leading __syncthreads() guards smem reuse
    }

    // epilogue: normalize, write
#pragma unroll
    for (int i = 0; i < 4; i++) {
        float invl = 1.f / l[i];
        float4 w = make_float4(oacc[i][0] * invl, oacc[i][1] * invl,
                               oacc[i][2] * invl, oacc[i][3] * invl);
        *(float4*)&Og[(size_t)(r0 + (rg << 2) + i) * HID + h * HD + (cg << 2)] = w;
    }
}

// ---------------- combine: ctx = rmsnorm(o1 - lam*o2) * subln * (1-lam_init) ----
__global__ __launch_bounds__(256)
void combine_kernel(const float* __restrict__ subln, float* __restrict__ ctx) {
    int warp = blockIdx.x * 8 + (threadIdx.x >> 5);
    int lane = threadIdx.x & 31;
    if (warp >= S * NH) return;
    int s = warp >> 5;
    int h = warp & 31;
    size_t base = (size_t)s * HID + h * HD + lane;
    float lam = g_lam;
    float c0 = g_O1[base]      - lam * g_O2[base];
    float c1 = g_O1[base + 32] - lam * g_O2[base + 32];
    float ss = c0 * c0 + c1 * c1;
#pragma unroll
    for (int o = 16; o >= 1; o >>= 1)
        ss += __shfl_xor_sync(0xffffffffu, ss, o);
    float inv = rsqrtf(ss * (1.f / 64.f) + 1e-6f);
    float sc  = inv * (1.f - (float)LAM_INIT);
    ctx[base]      = c0 * sc * subln[lane];
    ctx[base + 32] = c1 * sc * subln[lane + 32];
}

// ---------------- host launcher ----------------
extern "C" void kernel_launch(void* const* d_in, const int* in_sizes, int n_in,
                              void* d_out, int out_size) {
    const float* hid  = (const float*)d_in[0];
    const float* Wq   = (const float*)d_in[1];
    const float* Wk   = (const float*)d_in[2];
    const float* Wv   = (const float*)d_in[3];
    const float* Wo   = (const float*)d_in[4];
    const float* lq1  = (const float*)d_in[5];
    const float* lk1  = (const float*)d_in[6];
    const float* lq2  = (const float*)d_in[7];
    const float* lk2  = (const float*)d_in[8];
    const float* subw = (const float*)d_in[9];
    float* out = (float*)d_out;

    float *Q, *K, *V, *O1, *O2, *CTX;
    cudaGetSymbolAddress((void**)&Q,   g_Q);
    cudaGetSymbolAddress((void**)&K,   g_K);
    cudaGetSymbolAddress((void**)&V,   g_V);
    cudaGetSymbolAddress((void**)&O1,  g_O1);
    cudaGetSymbolAddress((void**)&O2,  g_O2);
    cudaGetSymbolAddress((void**)&CTX, g_CTX);

    const int FLASH_SMEM = (3 * 64 * 64 + 64 * PS_STRIDE) * (int)sizeof(float); // 66560 B
    cudaFuncSetAttribute(flash_attn_kernel,
                         cudaFuncAttributeMaxDynamicSharedMemorySize, FLASH_SMEM);

    // lambda + rope tables
    lam_kernel<<<1, 32>>>(lq1, lk1, lq2, lk2);
    rope_table_kernel<<<(S * 32 + 255) / 256, 256>>>();

    // projections
    sgemm_nt<<<dim3(Q_W / 128, S / 128), 256>>>(hid, Wq, Q, S, Q_W, HID);
    sgemm_nt<<<dim3(Q_W / 128, S / 128), 256>>>(hid, Wk, K, S, Q_W, HID);
    sgemm_nt<<<dim3(HID / 128, S / 128), 256>>>(hid, Wv, V, S, HID, HID);

    // RoPE on Q and K (both halves)
    rope_apply_kernel<<<(S * 2048 + 255) / 256, 256>>>(Q);
    rope_apply_kernel<<<(S * 2048 + 255) / 256, 256>>>(K);

    // two attention streams
    flash_attn_kernel<<<dim3(S / 64, NH), 256, FLASH_SMEM>>>(Q, K, V, O1, 0);
    flash_attn_kernel<<<dim3(S / 64, NH), 256, FLASH_SMEM>>>(Q, K, V, O2, HID);

    // differential combine + headwise RMSNorm
    combine_kernel<<<(S * NH + 7) / 8, 256>>>(subw, CTX);

    // output projection
    sgemm_nt<<<dim3(HID / 128, S / 128), 256>>>(CTX, Wo, out, S, HID, HID);
}

// round 4
// speedup vs baseline: 3.0991x; 3.0991x over previous
#include <cuda_runtime.h>
#include <math.h>

// ---------------- problem constants ----------------
#define S 2048
#define HID 2048
#define NH 32
#define HD 64
#define Q_W 4096            // 2*HID
#define SCALE 0.125f        // 1/sqrt(64)
#define LAM_INIT 0.7836057665316245
#define NEG_BIG (-1e30f)

// ---------------- scratch (device globals, no allocation) ----------------
__device__ float g_Q[(size_t)S * Q_W];
__device__ float g_K[(size_t)S * Q_W];
__device__ float g_V[(size_t)S * HID];
__device__ float g_O1[(size_t)S * HID];
__device__ float g_O2[(size_t)S * HID];
__device__ float g_CTX[(size_t)S * HID];
__device__ float g_cos[S * 32];
__device__ float g_sin[S * 32];
__device__ float g_lam;

// ---------------- tf32 helpers ----------------
__device__ __forceinline__ unsigned f2tf(float x) {
    unsigned r;
    asm("cvt.rna.tf32.f32 %0, %1;" : "=r"(r) : "f"(x));
    return r;
}
__device__ __forceinline__ void mma_tf32(float c[4],
                                         unsigned a0, unsigned a1, unsigned a2, unsigned a3,
                                         unsigned b0, unsigned b1) {
    asm volatile(
        "mma.sync.aligned.m16n8k8.row.col.f32.tf32.tf32.f32 "
        "{%0,%1,%2,%3},{%4,%5,%6,%7},{%8,%9},{%0,%1,%2,%3};"
        : "+f"(c[0]), "+f"(c[1]), "+f"(c[2]), "+f"(c[3])
        : "r"(a0), "r"(a1), "r"(a2), "r"(a3), "r"(b0), "r"(b1));
}

// ---------------- lambda scalar ----------------
__global__ void lam_kernel(const float* __restrict__ lq1, const float* __restrict__ lk1,
                           const float* __restrict__ lq2, const float* __restrict__ lk2) {
    if (threadIdx.x == 0) {
        float d1 = 0.f, d2 = 0.f;
        for (int i = 0; i < HD; i++) { d1 += lq1[i] * lk1[i]; d2 += lq2[i] * lk2[i]; }
        g_lam = expf(d1) - expf(d2) + (float)LAM_INIT;
    }
}

// ---------------- RoPE table (float64 like reference) ----------------
__global__ void rope_table_kernel() {
    int idx = blockIdx.x * blockDim.x + threadIdx.x;
    if (idx >= S * 32) return;
    int s = idx >> 5;
    int d = idx & 31;
    double inv = pow(10000.0, -(double)d / 32.0);
    double ang = (double)s * inv;
    g_cos[idx] = (float)cos(ang);
    g_sin[idx] = (float)sin(ang);
}

// ---------------- RoPE in-place on [S, 4096] ----------------
__global__ void rope_apply_kernel(float* __restrict__ X) {
    int idx = blockIdx.x * blockDim.x + threadIdx.x;   // S*2048 pairs
    if (idx >= S * 2048) return;
    int s    = idx >> 11;
    int p    = idx & 2047;
    int half = p >> 10;
    int rem  = p & 1023;
    int h    = rem >> 5;
    int d    = rem & 31;
    size_t base = (size_t)s * Q_W + half * HID + h * HD + d;
    float x1 = X[base];
    float x2 = X[base + 32];
    float c  = g_cos[s * 32 + d];
    float sn = g_sin[s * 32 + d];
    X[base]      = x1 * c - x2 * sn;
    X[base + 32] = x2 * c + x1 * sn;
}

// ================= TF32 GEMM: C[M,N] = A[M,K] @ B[N,K]^T =================
// block 128x128, BK=32, 8 warps (2m x 4n), warp tile 64x32 (4 x 4 mma tiles)
#define GA_STR 36
__global__ __launch_bounds__(256, 1)
void gemm_tf32_nt(const float* __restrict__ A, const float* __restrict__ B,
                  float* __restrict__ C, int M, int N, int K) {
    __shared__ unsigned As[128 * GA_STR];
    __shared__ unsigned Bs[128 * GA_STR];
    const int tid  = threadIdx.x;
    const int lane = tid & 31;
    const int warp = tid >> 5;
    const int wm = (warp >> 2) * 64;
    const int wn = (warp & 3) * 32;
    const int bm = blockIdx.y * 128;
    const int bn = blockIdx.x * 128;
    const int a  = lane >> 2;
    const int mm = lane & 3;

    float acc[4][4][4];
#pragma unroll
    for (int i = 0; i < 4; i++)
#pragma unroll
        for (int j = 0; j < 4; j++)
#pragma unroll
            for (int r = 0; r < 4; r++) acc[i][j][r] = 0.f;

    const float* Ab = A + (size_t)bm * K;
    const float* Bb = B + (size_t)bn * K;

    float4 ra[4], rb[4];
#pragma unroll
    for (int i = 0; i < 4; i++) {
        int lin = i * 256 + tid, row = lin >> 3, q = lin & 7;
        ra[i] = *(const float4*)(Ab + (size_t)row * K + q * 4);
        rb[i] = *(const float4*)(Bb + (size_t)row * K + q * 4);
    }

    for (int k0 = 0; k0 < K; k0 += 32) {
        __syncthreads();
#pragma unroll
        for (int i = 0; i < 4; i++) {
            int lin = i * 256 + tid, row = lin >> 3, q = lin & 7;
            unsigned* pa = &As[row * GA_STR + q * 4];
            pa[0] = f2tf(ra[i].x); pa[1] = f2tf(ra[i].y);
            pa[2] = f2tf(ra[i].z); pa[3] = f2tf(ra[i].w);
            unsigned* pb = &Bs[row * GA_STR + q * 4];
            pb[0] = f2tf(rb[i].x); pb[1] = f2tf(rb[i].y);
            pb[2] = f2tf(rb[i].z); pb[3] = f2tf(rb[i].w);
        }
        __syncthreads();
        if (k0 + 32 < K) {
#pragma unroll
            for (int i = 0; i < 4; i++) {
                int lin = i * 256 + tid, row = lin >> 3, q = lin & 7;
                ra[i] = *(const float4*)(Ab + (size_t)row * K + k0 + 32 + q * 4);
                rb[i] = *(const float4*)(Bb + (size_t)row * K + k0 + 32 + q * 4);
            }
        }
#pragma unroll
        for (int k8 = 0; k8 < 4; k8++) {
            unsigned af[4][4], bf[4][2];
#pragma unroll
            for (int i = 0; i < 4; i++) {
                const unsigned* p  = &As[(wm + i * 16 + a) * GA_STR + k8 * 8 + mm];
                const unsigned* p2 = p + 8 * GA_STR;
                af[i][0] = p[0];  af[i][2] = p[4];
                af[i][1] = p2[0]; af[i][3] = p2[4];
            }
#pragma unroll
            for (int j = 0; j < 4; j++) {
                const unsigned* p = &Bs[(wn + j * 8 + a) * GA_STR + k8 * 8 + mm];
                bf[j][0] = p[0]; bf[j][1] = p[4];
            }
#pragma unroll
            for (int i = 0; i < 4; i++)
#pragma unroll
                for (int j = 0; j < 4; j++)
                    mma_tf32(acc[i][j], af[i][0], af[i][1], af[i][2], af[i][3],
                             bf[j][0], bf[j][1]);
        }
    }

#pragma unroll
    for (int i = 0; i < 4; i++) {
        int row = bm + wm + i * 16 + a;
#pragma unroll
        for (int j = 0; j < 4; j++) {
            int col = bn + wn + j * 8 + mm * 2;
            *(float2*)&C[(size_t)row * N + col]       = make_float2(acc[i][j][0], acc[i][j][1]);
            *(float2*)&C[(size_t)(row + 8) * N + col] = make_float2(acc[i][j][2], acc[i][j][3]);
        }
    }
}

// ================= TF32 flash attention (both streams via blockIdx.z) ======
// q-block 128 rows, 8 warps each own m16 x full n; kv tiles of 64.
#define QS_STR 68
#define KS_STR 68
#define VS_STR 72
#define PS_STR 68
#define QS_OFF 0
#define KS_OFF (128 * QS_STR)                 // 8704
#define VS_OFF (KS_OFF + 64 * KS_STR)         // 13056
#define PS_OFF (VS_OFF + 64 * VS_STR)         // 17664
#define FLASH_WORDS (PS_OFF + 128 * PS_STR)   // 26368
#define FLASH_BYTES (FLASH_WORDS * 4)         // 105472

__global__ __launch_bounds__(256, 2)
void flash_tf32(const float* __restrict__ Qg, const float* __restrict__ Kg,
                const float* __restrict__ Vg,
                float* __restrict__ O1g, float* __restrict__ O2g) {
    extern __shared__ unsigned smw[];
    unsigned* Qs = smw + QS_OFF;
    unsigned* Ks = smw + KS_OFF;
    unsigned* Vs = smw + VS_OFF;
    unsigned* Ps = smw + PS_OFF;

    const int tid  = threadIdx.x;
    const int lane = tid & 31;
    const int warp = tid >> 5;
    const int a  = lane >> 2;
    const int mm = lane & 3;
    const int qi = gridDim.x - 1 - blockIdx.x;   // heavy tiles first
    const int h  = blockIdx.y;
    const int st = blockIdx.z;
    const int coff = st * HID + h * HD;
    float* Og = st ? O2g : O1g;
    const int r0 = qi * 128;
    const int m0 = warp * 16;
    const int rA = m0 + a;

    // load Q tile (rope already applied in gmem)
#pragma unroll
    for (int i = 0; i < 8; i++) {
        int lin = i * 256 + tid, row = lin >> 4, q = lin & 15;
        float4 v = *(const float4*)(Qg + (size_t)(r0 + row) * Q_W + coff + q * 4);
        unsigned* p = &Qs[row * QS_STR + q * 4];
        p[0] = f2tf(v.x); p[1] = f2tf(v.y); p[2] = f2tf(v.z); p[3] = f2tf(v.w);
    }

    float oacc[8][4];
#pragma unroll
    for (int j = 0; j < 8; j++)
#pragma unroll
        for (int r = 0; r < 4; r++) oacc[j][r] = 0.f;
    float mr0 = NEG_BIG, mr1 = NEG_BIG, lr0 = 0.f, lr1 = 0.f;

    const int ktmax = 2 * qi + 1;
    for (int kt = 0; kt <= ktmax; kt++) {
        int c0 = kt * 64;
        float4 rk[4], rv[4];
#pragma unroll
        for (int i = 0; i < 4; i++) {
            int lin = i * 256 + tid, row = lin >> 4, q = lin & 15;
            rk[i] = *(const float4*)(Kg + (size_t)(c0 + row) * Q_W + coff + q * 4);
            rv[i] = *(const float4*)(Vg + (size_t)(c0 + row) * HID + h * HD + q * 4);
        }
        __syncthreads();
#pragma unroll
        for (int i = 0; i < 4; i++) {
            int lin = i * 256 + tid, row = lin >> 4, q = lin & 15;
            unsigned* pk = &Ks[row * KS_STR + q * 4];
            pk[0] = f2tf(rk[i].x); pk[1] = f2tf(rk[i].y);
            pk[2] = f2tf(rk[i].z); pk[3] = f2tf(rk[i].w);
            unsigned* pv = &Vs[row * VS_STR + q * 4];
            pv[0] = f2tf(rv[i].x); pv[1] = f2tf(rv[i].y);
            pv[2] = f2tf(rv[i].z); pv[3] = f2tf(rv[i].w);
        }
        __syncthreads();

        // ---- S = Q K^T ----
        float sacc[8][4];
#pragma unroll
        for (int j = 0; j < 8; j++)
#pragma unroll
            for (int r = 0; r < 4; r++) sacc[j][r] = 0.f;

#pragma unroll
        for (int d8 = 0; d8 < 8; d8++) {
            unsigned a0 = Qs[rA * QS_STR + d8 * 8 + mm];
            unsigned a2 = Qs[rA * QS_STR + d8 * 8 + mm + 4];
            unsigned a1 = Qs[(rA + 8) * QS_STR + d8 * 8 + mm];
            unsigned a3 = Qs[(rA + 8) * QS_STR + d8 * 8 + mm + 4];
#pragma unroll
            for (int j = 0; j < 8; j++) {
                unsigned b0 = Ks[(j * 8 + a) * KS_STR + d8 * 8 + mm];
                unsigned b1 = Ks[(j * 8 + a) * KS_STR + d8 * 8 + mm + 4];
                mma_tf32(sacc[j], a0, a1, a2, a3, b0, b1);
            }
        }

        // ---- scale + causal mask ----
        bool dmask = (kt >= 2 * qi);
#pragma unroll
        for (int j = 0; j < 8; j++) {
#pragma unroll
            for (int r = 0; r < 4; r++) {
                float v = sacc[j][r] * SCALE;
                if (dmask) {
                    int gr = r0 + m0 + a + ((r >> 1) << 3);
                    int gc = c0 + j * 8 + mm * 2 + (r & 1);
                    if (gc > gr) v = NEG_BIG;
                }
                sacc[j][r] = v;
            }
        }

        // ---- online softmax (rows owned within 4-lane groups) ----
        float mx0 = NEG_BIG, mx1 = NEG_BIG;
#pragma unroll
        for (int j = 0; j < 8; j++) {
            mx0 = fmaxf(mx0, fmaxf(sacc[j][0], sacc[j][1]));
            mx1 = fmaxf(mx1, fmaxf(sacc[j][2], sacc[j][3]));
        }
        mx0 = fmaxf(mx0, __shfl_xor_sync(0xffffffffu, mx0, 1));
        mx0 = fmaxf(mx0, __shfl_xor_sync(0xffffffffu, mx0, 2));
        mx1 = fmaxf(mx1, __shfl_xor_sync(0xffffffffu, mx1, 1));
        mx1 = fmaxf(mx1, __shfl_xor_sync(0xffffffffu, mx1, 2));
        float mn0 = fmaxf(mr0, mx0), mn1 = fmaxf(mr1, mx1);
        float corr0 = __expf(mr0 - mn0), corr1 = __expf(mr1 - mn1);
        mr0 = mn0; mr1 = mn1;

        float ps0 = 0.f, ps1 = 0.f;
#pragma unroll
        for (int j = 0; j < 8; j++) {
            float p0 = __expf(sacc[j][0] - mn0);
            float p1 = __expf(sacc[j][1] - mn0);
            float p2 = __expf(sacc[j][2] - mn1);
            float p3 = __expf(sacc[j][3] - mn1);
            ps0 += p0 + p1; ps1 += p2 + p3;
            int col = j * 8 + mm * 2;
            Ps[rA * PS_STR + col]           = f2tf(p0);
            Ps[rA * PS_STR + col + 1]       = f2tf(p1);
            Ps[(rA + 8) * PS_STR + col]     = f2tf(p2);
            Ps[(rA + 8) * PS_STR + col + 1] = f2tf(p3);
        }
        ps0 += __shfl_xor_sync(0xffffffffu, ps0, 1);
        ps0 += __shfl_xor_sync(0xffffffffu, ps0, 2);
        ps1 += __shfl_xor_sync(0xffffffffu, ps1, 1);
        ps1 += __shfl_xor_sync(0xffffffffu, ps1, 2);
        lr0 = lr0 * corr0 + ps0;
        lr1 = lr1 * corr1 + ps1;
#pragma unroll
        for (int j = 0; j < 8; j++) {
            oacc[j][0] *= corr0; oacc[j][1] *= corr0;
            oacc[j][2] *= corr1; oacc[j][3] *= corr1;
        }
        __syncwarp();

        // ---- O += P V ----
#pragma unroll
        for (int kv8 = 0; kv8 < 8; kv8++) {
            unsigned a0 = Ps[rA * PS_STR + kv8 * 8 + mm];
            unsigned a2 = Ps[rA * PS_STR + kv8 * 8 + mm + 4];
            unsigned a1 = Ps[(rA + 8) * PS_STR + kv8 * 8 + mm];
            unsigned a3 = Ps[(rA + 8) * PS_STR + kv8 * 8 + mm + 4];
#pragma unroll
            for (int j = 0; j < 8; j++) {
                unsigned b0 = Vs[(kv8 * 8 + mm) * VS_STR + j * 8 + a];
                unsigned b1 = Vs[(kv8 * 8 + mm + 4) * VS_STR + j * 8 + a];
                mma_tf32(oacc[j], a0, a1, a2, a3, b0, b1);
            }
        }
    }

    // ---- epilogue: normalize + write ----
    float il0 = 1.f / lr0, il1 = 1.f / lr1;
#pragma unroll
    for (int j = 0; j < 8; j++) {
        int col = j * 8 + mm * 2;
        *(float2*)&Og[(size_t)(r0 + m0 + a) * HID + h * HD + col] =
            make_float2(oacc[j][0] * il0, oacc[j][1] * il0);
        *(float2*)&Og[(size_t)(r0 + m0 + a + 8) * HID + h * HD + col] =
            make_float2(oacc[j][2] * il1, oacc[j][3] * il1);
    }
}

// ---------------- combine: ctx = rmsnorm(o1 - lam*o2) * subln * (1-lam_init) ----
__global__ __launch_bounds__(256)
void combine_kernel(const float* __restrict__ subln, float* __restrict__ ctx) {
    int warp = blockIdx.x * 8 + (threadIdx.x >> 5);
    int lane = threadIdx.x & 31;
    if (warp >= S * NH) return;
    int s = warp >> 5;
    int h = warp & 31;
    size_t base = (size_t)s * HID + h * HD + lane;
    float lam = g_lam;
    float c0 = g_O1[base]      - lam * g_O2[base];
    float c1 = g_O1[base + 32] - lam * g_O2[base + 32];
    float ss = c0 * c0 + c1 * c1;
#pragma unroll
    for (int o = 16; o >= 1; o >>= 1)
        ss += __shfl_xor_sync(0xffffffffu, ss, o);
    float inv = rsqrtf(ss * (1.f / 64.f) + 1e-6f);
    float sc  = inv * (1.f - (float)LAM_INIT);
    ctx[base]      = c0 * sc * subln[lane];
    ctx[base + 32] = c1 * sc * subln[lane + 32];
}

// ---------------- host launcher ----------------
extern "C" void kernel_launch(void* const* d_in, const int* in_sizes, int n_in,
                              void* d_out, int out_size) {
    const float* hid  = (const float*)d_in[0];
    const float* Wq   = (const float*)d_in[1];
    const float* Wk   = (const float*)d_in[2];
    const float* Wv   = (const float*)d_in[3];
    const float* Wo   = (const float*)d_in[4];
    const float* lq1  = (const float*)d_in[5];
    const float* lk1  = (const float*)d_in[6];
    const float* lq2  = (const float*)d_in[7];
    const float* lk2  = (const float*)d_in[8];
    const float* subw = (const float*)d_in[9];
    float* out = (float*)d_out;

    float *Q, *K, *V, *O1, *O2, *CTX;
    cudaGetSymbolAddress((void**)&Q,   g_Q);
    cudaGetSymbolAddress((void**)&K,   g_K);
    cudaGetSymbolAddress((void**)&V,   g_V);
    cudaGetSymbolAddress((void**)&O1,  g_O1);
    cudaGetSymbolAddress((void**)&O2,  g_O2);
    cudaGetSymbolAddress((void**)&CTX, g_CTX);

    cudaFuncSetAttribute(flash_tf32,
                         cudaFuncAttributeMaxDynamicSharedMemorySize, FLASH_BYTES);

    // lambda + rope table
    lam_kernel<<<1, 32>>>(lq1, lk1, lq2, lk2);
    rope_table_kernel<<<(S * 32 + 255) / 256, 256>>>();

    // projections (tf32 tensor core)
    gemm_tf32_nt<<<dim3(Q_W / 128, S / 128), 256>>>(hid, Wq, Q, S, Q_W, HID);
    gemm_tf32_nt<<<dim3(Q_W / 128, S / 128), 256>>>(hid, Wk, K, S, Q_W, HID);
    gemm_tf32_nt<<<dim3(HID / 128, S / 128), 256>>>(hid, Wv, V, S, HID, HID);

    // RoPE on Q and K (both halves)
    rope_apply_kernel<<<(S * 2048 + 255) / 256, 256>>>(Q);
    rope_apply_kernel<<<(S * 2048 + 255) / 256, 256>>>(K);

    // both differential-attention streams in one launch
    flash_tf32<<<dim3(S / 128, NH, 2), 256, FLASH_BYTES>>>(Q, K, V, O1, O2);

    // differential combine + headwise RMSNorm
    combine_kernel<<<(S * NH + 7) / 8, 256>>>(subw, CTX);

    // output projection
    gemm_tf32_nt<<<dim3(HID / 128, S / 128), 256>>>(CTX, Wo, out, S, HID, HID);
}

// round 5
// speedup vs baseline: 3.1634x; 1.0207x over previous
#include <cuda_runtime.h>
#include <math.h>

// ---------------- problem constants ----------------
#define S 2048
#define HID 2048
#define NH 32
#define HD 64
#define Q_W 4096            // 2*HID
#define SCALE 0.125f        // 1/sqrt(64)
#define LAM_INIT 0.7836057665316245
#define NEG_BIG (-1e30f)

// ---------------- scratch (device globals, no allocation) ----------------
__device__ float g_Q[(size_t)S * Q_W];
__device__ float g_K[(size_t)S * Q_W];
__device__ float g_V[(size_t)S * HID];
__device__ float g_O1[(size_t)S * HID];
__device__ float g_O2[(size_t)S * HID];
__device__ float g_CTX[(size_t)S * HID];
__device__ float g_cos[S * 32];
__device__ float g_sin[S * 32];
__device__ float g_lam;

// ---------------- tf32 helpers ----------------
__device__ __forceinline__ unsigned f2tf(float x) {
    unsigned r;
    asm("cvt.rna.tf32.f32 %0, %1;" : "=r"(r) : "f"(x));
    return r;
}
__device__ __forceinline__ void mma_tf32(float c[4],
                                         unsigned a0, unsigned a1, unsigned a2, unsigned a3,
                                         unsigned b0, unsigned b1) {
    asm volatile(
        "mma.sync.aligned.m16n8k8.row.col.f32.tf32.tf32.f32 "
        "{%0,%1,%2,%3},{%4,%5,%6,%7},{%8,%9},{%0,%1,%2,%3};"
        : "+f"(c[0]), "+f"(c[1]), "+f"(c[2]), "+f"(c[3])
        : "r"(a0), "r"(a1), "r"(a2), "r"(a3), "r"(b0), "r"(b1));
}

// ---------------- lambda scalar ----------------
__global__ void lam_kernel(const float* __restrict__ lq1, const float* __restrict__ lk1,
                           const float* __restrict__ lq2, const float* __restrict__ lk2) {
    if (threadIdx.x == 0) {
        float d1 = 0.f, d2 = 0.f;
        for (int i = 0; i < HD; i++) { d1 += lq1[i] * lk1[i]; d2 += lq2[i] * lk2[i]; }
        g_lam = expf(d1) - expf(d2) + (float)LAM_INIT;
    }
}

// ---------------- RoPE table (float64 like reference) ----------------
__global__ void rope_table_kernel() {
    int idx = blockIdx.x * blockDim.x + threadIdx.x;
    if (idx >= S * 32) return;
    int s = idx >> 5;
    int d = idx & 31;
    double inv = pow(10000.0, -(double)d / 32.0);
    double ang = (double)s * inv;
    g_cos[idx] = (float)cos(ang);
    g_sin[idx] = (float)sin(ang);
}

// ---------------- RoPE in-place on [S, 4096] ----------------
__global__ void rope_apply_kernel(float* __restrict__ X) {
    int idx = blockIdx.x * blockDim.x + threadIdx.x;   // S*2048 pairs
    if (idx >= S * 2048) return;
    int s    = idx >> 11;
    int p    = idx & 2047;
    int half = p >> 10;
    int rem  = p & 1023;
    int h    = rem >> 5;
    int d    = rem & 31;
    size_t base = (size_t)s * Q_W + half * HID + h * HD + d;
    float x1 = X[base];
    float x2 = X[base + 32];
    float c  = g_cos[s * 32 + d];
    float sn = g_sin[s * 32 + d];
    X[base]      = x1 * c - x2 * sn;
    X[base + 32] = x2 * c + x1 * sn;
}

// ================= TF32 GEMM: C[M,N] = A[M,K] @ B[N,K]^T =================
// block 128x128, BK=32, 8 warps (2m x 4n), warp tile 64x32 (4 x 4 mma tiles)
// Double-buffered smem (2 stages), one __syncthreads per k-tile:
//   LDG(next) -> mma(cur) -> STS(cur^1) -> sync
#define GA_STR 36
#define STAGE_A (128 * GA_STR)             // words per A buffer
#define STAGE_W (2 * STAGE_A)              // words per stage (A + B)
#define GEMM_SMEM_BYTES (2 * STAGE_W * 4)  // 2 stages

__global__ __launch_bounds__(256, 1)
void gemm_tf32_nt(const float* __restrict__ A, const float* __restrict__ B,
                  float* __restrict__ C, int M, int N, int K) {
    extern __shared__ unsigned gsm[];
    const int tid  = threadIdx.x;
    const int lane = tid & 31;
    const int warp = tid >> 5;
    const int wm = (warp >> 2) * 64;
    const int wn = (warp & 3) * 32;
    const int bm = blockIdx.y * 128;
    const int bn = blockIdx.x * 128;
    const int a  = lane >> 2;
    const int mm = lane & 3;

    float acc[4][4][4];
#pragma unroll
    for (int i = 0; i < 4; i++)
#pragma unroll
        for (int j = 0; j < 4; j++)
#pragma unroll
            for (int r = 0; r < 4; r++) acc[i][j][r] = 0.f;

    const float* Ab = A + (size_t)bm * K;
    const float* Bb = B + (size_t)bn * K;

    // per-thread store coordinates (same for every stage)
    int srow[4], sq[4];
#pragma unroll
    for (int i = 0; i < 4; i++) {
        int lin = i * 256 + tid;
        srow[i] = lin >> 3;
        sq[i]   = lin & 7;
    }

    float4 ra[4], rb[4];
    // preload tile 0
#pragma unroll
    for (int i = 0; i < 4; i++) {
        ra[i] = *(const float4*)(Ab + (size_t)srow[i] * K + sq[i] * 4);
        rb[i] = *(const float4*)(Bb + (size_t)srow[i] * K + sq[i] * 4);
    }
    // store stage 0
    {
        unsigned* As = gsm;
        unsigned* Bs = gsm + STAGE_A;
#pragma unroll
        for (int i = 0; i < 4; i++) {
            unsigned* pa = &As[srow[i] * GA_STR + sq[i] * 4];
            pa[0] = f2tf(ra[i].x); pa[1] = f2tf(ra[i].y);
            pa[2] = f2tf(ra[i].z); pa[3] = f2tf(ra[i].w);
            unsigned* pb = &Bs[srow[i] * GA_STR + sq[i] * 4];
            pb[0] = f2tf(rb[i].x); pb[1] = f2tf(rb[i].y);
            pb[2] = f2tf(rb[i].z); pb[3] = f2tf(rb[i].w);
        }
    }
    __syncthreads();

    int cur = 0;
    for (int k0 = 0; k0 < K; k0 += 32) {
        const bool has_next = (k0 + 32 < K);
        if (has_next) {
#pragma unroll
            for (int i = 0; i < 4; i++) {
                ra[i] = *(const float4*)(Ab + (size_t)srow[i] * K + k0 + 32 + sq[i] * 4);
                rb[i] = *(const float4*)(Bb + (size_t)srow[i] * K + k0 + 32 + sq[i] * 4);
            }
        }

        const unsigned* As = gsm + cur * STAGE_W;
        const unsigned* Bs = As + STAGE_A;
#pragma unroll
        for (int k8 = 0; k8 < 4; k8++) {
            unsigned af[4][4], bf[4][2];
#pragma unroll
            for (int i = 0; i < 4; i++) {
                const unsigned* p  = &As[(wm + i * 16 + a) * GA_STR + k8 * 8 + mm];
                const unsigned* p2 = p + 8 * GA_STR;
                af[i][0] = p[0];  af[i][2] = p[4];
                af[i][1] = p2[0]; af[i][3] = p2[4];
            }
#pragma unroll
            for (int j = 0; j < 4; j++) {
                const unsigned* p = &Bs[(wn + j * 8 + a) * GA_STR + k8 * 8 + mm];
                bf[j][0] = p[0]; bf[j][1] = p[4];
            }
#pragma unroll
            for (int i = 0; i < 4; i++)
#pragma unroll
                for (int j = 0; j < 4; j++)
                    mma_tf32(acc[i][j], af[i][0], af[i][1], af[i][2], af[i][3],
                             bf[j][0], bf[j][1]);
        }

        if (has_next) {
            unsigned* Asn = gsm + (cur ^ 1) * STAGE_W;
            unsigned* Bsn = Asn + STAGE_A;
#pragma unroll
            for (int i = 0; i < 4; i++) {
                unsigned* pa = &Asn[srow[i] * GA_STR + sq[i] * 4];
                pa[0] = f2tf(ra[i].x); pa[1] = f2tf(ra[i].y);
                pa[2] = f2tf(ra[i].z); pa[3] = f2tf(ra[i].w);
                unsigned* pb = &Bsn[srow[i] * GA_STR + sq[i] * 4];
                pb[0] = f2tf(rb[i].x); pb[1] = f2tf(rb[i].y);
                pb[2] = f2tf(rb[i].z); pb[3] = f2tf(rb[i].w);
            }
            __syncthreads();
        }
        cur ^= 1;
    }

#pragma unroll
    for (int i = 0; i < 4; i++) {
        int row = bm + wm + i * 16 + a;
#pragma unroll
        for (int j = 0; j < 4; j++) {
            int col = bn + wn + j * 8 + mm * 2;
            *(float2*)&C[(size_t)row * N + col]       = make_float2(acc[i][j][0], acc[i][j][1]);
            *(float2*)&C[(size_t)(row + 8) * N + col] = make_float2(acc[i][j][2], acc[i][j][3]);
        }
    }
}

// ================= TF32 flash attention (both streams via blockIdx.z) ======
// q-block 128 rows, 8 warps each own m16 x full n; kv tiles of 64.
#define QS_STR 68
#define KS_STR 68
#define VS_STR 72
#define PS_STR 68
#define QS_OFF 0
#define KS_OFF (128 * QS_STR)                 // 8704
#define VS_OFF (KS_OFF + 64 * KS_STR)         // 13056
#define PS_OFF (VS_OFF + 64 * VS_STR)         // 17664
#define FLASH_WORDS (PS_OFF + 128 * PS_STR)   // 26368
#define FLASH_BYTES (FLASH_WORDS * 4)         // 105472

__global__ __launch_bounds__(256, 2)
void flash_tf32(const float* __restrict__ Qg, const float* __restrict__ Kg,
                const float* __restrict__ Vg,
                float* __restrict__ O1g, float* __restrict__ O2g) {
    extern __shared__ unsigned smw[];
    unsigned* Qs = smw + QS_OFF;
    unsigned* Ks = smw + KS_OFF;
    unsigned* Vs = smw + VS_OFF;
    unsigned* Ps = smw + PS_OFF;

    const int tid  = threadIdx.x;
    const int lane = tid & 31;
    const int warp = tid >> 5;
    const int a  = lane >> 2;
    const int mm = lane & 3;
    const int qi = gridDim.x - 1 - blockIdx.x;   // heavy tiles first
    const int h  = blockIdx.y;
    const int st = blockIdx.z;
    const int coff = st * HID + h * HD;
    float* Og = st ? O2g : O1g;
    const int r0 = qi * 128;
    const int m0 = warp * 16;
    const int rA = m0 + a;

    // load Q tile (rope already applied in gmem)
#pragma unroll
    for (int i = 0; i < 8; i++) {
        int lin = i * 256 + tid, row = lin >> 4, q = lin & 15;
        float4 v = *(const float4*)(Qg + (size_t)(r0 + row) * Q_W + coff + q * 4);
        unsigned* p = &Qs[row * QS_STR + q * 4];
        p[0] = f2tf(v.x); p[1] = f2tf(v.y); p[2] = f2tf(v.z); p[3] = f2tf(v.w);
    }

    float oacc[8][4];
#pragma unroll
    for (int j = 0; j < 8; j++)
#pragma unroll
        for (int r = 0; r < 4; r++) oacc[j][r] = 0.f;
    float mr0 = NEG_BIG, mr1 = NEG_BIG, lr0 = 0.f, lr1 = 0.f;

    const int ktmax = 2 * qi + 1;
    for (int kt = 0; kt <= ktmax; kt++) {
        int c0 = kt * 64;
        float4 rk[4], rv[4];
#pragma unroll
        for (int i = 0; i < 4; i++) {
            int lin = i * 256 + tid, row = lin >> 4, q = lin & 15;
            rk[i] = *(const float4*)(Kg + (size_t)(c0 + row) * Q_W + coff + q * 4);
            rv[i] = *(const float4*)(Vg + (size_t)(c0 + row) * HID + h * HD + q * 4);
        }
        __syncthreads();
#pragma unroll
        for (int i = 0; i < 4; i++) {
            int lin = i * 256 + tid, row = lin >> 4, q = lin & 15;
            unsigned* pk = &Ks[row * KS_STR + q * 4];
            pk[0] = f2tf(rk[i].x); pk[1] = f2tf(rk[i].y);
            pk[2] = f2tf(rk[i].z); pk[3] = f2tf(rk[i].w);
            unsigned* pv = &Vs[row * VS_STR + q * 4];
            pv[0] = f2tf(rv[i].x); pv[1] = f2tf(rv[i].y);
            pv[2] = f2tf(rv[i].z); pv[3] = f2tf(rv[i].w);
        }
        __syncthreads();

        // ---- S = Q K^T ----
        float sacc[8][4];
#pragma unroll
        for (int j = 0; j < 8; j++)
#pragma unroll
            for (int r = 0; r < 4; r++) sacc[j][r] = 0.f;

#pragma unroll
        for (int d8 = 0; d8 < 8; d8++) {
            unsigned a0 = Qs[rA * QS_STR + d8 * 8 + mm];
            unsigned a2 = Qs[rA * QS_STR + d8 * 8 + mm + 4];
            unsigned a1 = Qs[(rA + 8) * QS_STR + d8 * 8 + mm];
            unsigned a3 = Qs[(rA + 8) * QS_STR + d8 * 8 + mm + 4];
#pragma unroll
            for (int j = 0; j < 8; j++) {
                unsigned b0 = Ks[(j * 8 + a) * KS_STR + d8 * 8 + mm];
                unsigned b1 = Ks[(j * 8 + a) * KS_STR + d8 * 8 + mm + 4];
                mma_tf32(sacc[j], a0, a1, a2, a3, b0, b1);
            }
        }

        // ---- scale + causal mask ----
        bool dmask = (kt >= 2 * qi);
#pragma unroll
        for (int j = 0; j < 8; j++) {
#pragma unroll
            for (int r = 0; r < 4; r++) {
                float v = sacc[j][r] * SCALE;
                if (dmask) {
                    int gr = r0 + m0 + a + ((r >> 1) << 3);
                    int gc = c0 + j * 8 + mm * 2 + (r & 1);
                    if (gc > gr) v = NEG_BIG;
                }
                sacc[j][r] = v;
            }
        }

        // ---- online softmax (rows owned within 4-lane groups) ----
        float mx0 = NEG_BIG, mx1 = NEG_BIG;
#pragma unroll
        for (int j = 0; j < 8; j++) {
            mx0 = fmaxf(mx0, fmaxf(sacc[j][0], sacc[j][1]));
            mx1 = fmaxf(mx1, fmaxf(sacc[j][2], sacc[j][3]));
        }
        mx0 = fmaxf(mx0, __shfl_xor_sync(0xffffffffu, mx0, 1));
        mx0 = fmaxf(mx0, __shfl_xor_sync(0xffffffffu, mx0, 2));
        mx1 = fmaxf(mx1, __shfl_xor_sync(0xffffffffu, mx1, 1));
        mx1 = fmaxf(mx1, __shfl_xor_sync(0xffffffffu, mx1, 2));
        float mn0 = fmaxf(mr0, mx0), mn1 = fmaxf(mr1, mx1);
        float corr0 = __expf(mr0 - mn0), corr1 = __expf(mr1 - mn1);
        mr0 = mn0; mr1 = mn1;

        float ps0 = 0.f, ps1 = 0.f;
#pragma unroll
        for (int j = 0; j < 8; j++) {
            float p0 = __expf(sacc[j][0] - mn0);
            float p1 = __expf(sacc[j][1] - mn0);
            float p2 = __expf(sacc[j][2] - mn1);
            float p3 = __expf(sacc[j][3] - mn1);
            ps0 += p0 + p1; ps1 += p2 + p3;
            int col = j * 8 + mm * 2;
            Ps[rA * PS_STR + col]           = f2tf(p0);
            Ps[rA * PS_STR + col + 1]       = f2tf(p1);
            Ps[(rA + 8) * PS_STR + col]     = f2tf(p2);
            Ps[(rA + 8) * PS_STR + col + 1] = f2tf(p3);
        }
        ps0 += __shfl_xor_sync(0xffffffffu, ps0, 1);
        ps0 += __shfl_xor_sync(0xffffffffu, ps0, 2);
        ps1 += __shfl_xor_sync(0xffffffffu, ps1, 1);
        ps1 += __shfl_xor_sync(0xffffffffu, ps1, 2);
        lr0 = lr0 * corr0 + ps0;
        lr1 = lr1 * corr1 + ps1;
#pragma unroll
        for (int j = 0; j < 8; j++) {
            oacc[j][0] *= corr0; oacc[j][1] *= corr0;
            oacc[j][2] *= corr1; oacc[j][3] *= corr1;
        }
        __syncwarp();

        // ---- O += P V ----
#pragma unroll
        for (int kv8 = 0; kv8 < 8; kv8++) {
            unsigned a0 = Ps[rA * PS_STR + kv8 * 8 + mm];
            unsigned a2 = Ps[rA * PS_STR + kv8 * 8 + mm + 4];
            unsigned a1 = Ps[(rA + 8) * PS_STR + kv8 * 8 + mm];
            unsigned a3 = Ps[(rA + 8) * PS_STR + kv8 * 8 + mm + 4];
#pragma unroll
            for (int j = 0; j < 8; j++) {
                unsigned b0 = Vs[(kv8 * 8 + mm) * VS_STR + j * 8 + a];
                unsigned b1 = Vs[(kv8 * 8 + mm + 4) * VS_STR + j * 8 + a];
                mma_tf32(oacc[j], a0, a1, a2, a3, b0, b1);
            }
        }
    }

    // ---- epilogue: normalize + write ----
    float il0 = 1.f / lr0, il1 = 1.f / lr1;
#pragma unroll
    for (int j = 0; j < 8; j++) {
        int col = j * 8 + mm * 2;
        *(float2*)&Og[(size_t)(r0 + m0 + a) * HID + h * HD + col] =
            make_float2(oacc[j][0] * il0, oacc[j][1] * il0);
        *(float2*)&Og[(size_t)(r0 + m0 + a + 8) * HID + h * HD + col] =
            make_float2(oacc[j][2] * il1, oacc[j][3] * il1);
    }
}

// ---------------- combine: ctx = rmsnorm(o1 - lam*o2) * subln * (1-lam_init) ----
__global__ __launch_bounds__(256)
void combine_kernel(const float* __restrict__ subln, float* __restrict__ ctx) {
    int warp = blockIdx.x * 8 + (threadIdx.x >> 5);
    int lane = threadIdx.x & 31;
    if (warp >= S * NH) return;
    int s = warp >> 5;
    int h = warp & 31;
    size_t base = (size_t)s * HID + h * HD + lane;
    float lam = g_lam;
    float c0 = g_O1[base]      - lam * g_O2[base];
    float c1 = g_O1[base + 32] - lam * g_O2[base + 32];
    float ss = c0 * c0 + c1 * c1;
#pragma unroll
    for (int o = 16; o >= 1; o >>= 1)
        ss += __shfl_xor_sync(0xffffffffu, ss, o);
    float inv = rsqrtf(ss * (1.f / 64.f) + 1e-6f);
    float sc  = inv * (1.f - (float)LAM_INIT);
    ctx[base]      = c0 * sc * subln[lane];
    ctx[base + 32] = c1 * sc * subln[lane + 32];
}

// ---------------- host launcher ----------------
extern "C" void kernel_launch(void* const* d_in, const int* in_sizes, int n_in,
                              void* d_out, int out_size) {
    const float* hid  = (const float*)d_in[0];
    const float* Wq   = (const float*)d_in[1];
    const float* Wk   = (const float*)d_in[2];
    const float* Wv   = (const float*)d_in[3];
    const float* Wo   = (const float*)d_in[4];
    const float* lq1  = (const float*)d_in[5];
    const float* lk1  = (const float*)d_in[6];
    const float* lq2  = (const float*)d_in[7];
    const float* lk2  = (const float*)d_in[8];
    const float* subw = (const float*)d_in[9];
    float* out = (float*)d_out;

    float *Q, *K, *V, *O1, *O2, *CTX;
    cudaGetSymbolAddress((void**)&Q,   g_Q);
    cudaGetSymbolAddress((void**)&K,   g_K);
    cudaGetSymbolAddress((void**)&V,   g_V);
    cudaGetSymbolAddress((void**)&O1,  g_O1);
    cudaGetSymbolAddress((void**)&O2,  g_O2);
    cudaGetSymbolAddress((void**)&CTX, g_CTX);

    cudaFuncSetAttribute(flash_tf32,
                         cudaFuncAttributeMaxDynamicSharedMemorySize, FLASH_BYTES);
    cudaFuncSetAttribute(gemm_tf32_nt,
                         cudaFuncAttributeMaxDynamicSharedMemorySize, GEMM_SMEM_BYTES);

    // lambda + rope table
    lam_kernel<<<1, 32>>>(lq1, lk1, lq2, lk2);
    rope_table_kernel<<<(S * 32 + 255) / 256, 256>>>();

    // projections (tf32 tensor core, double-buffered)
    gemm_tf32_nt<<<dim3(Q_W / 128, S / 128), 256, GEMM_SMEM_BYTES>>>(hid, Wq, Q, S, Q_W, HID);
    gemm_tf32_nt<<<dim3(Q_W / 128, S / 128), 256, GEMM_SMEM_BYTES>>>(hid, Wk, K, S, Q_W, HID);
    gemm_tf32_nt<<<dim3(HID / 128, S / 128), 256, GEMM_SMEM_BYTES>>>(hid, Wv, V, S, HID, HID);

    // RoPE on Q and K (both halves)
    rope_apply_kernel<<<(S * 2048 + 255) / 256, 256>>>(Q);
    rope_apply_kernel<<<(S * 2048 + 255) / 256, 256>>>(K);

    // both differential-attention streams in one launch
    flash_tf32<<<dim3(S / 128, NH, 2), 256, FLASH_BYTES>>>(Q, K, V, O1, O2);

    // differential combine + headwise RMSNorm
    combine_kernel<<<(S * NH + 7) / 8, 256>>>(subw, CTX);

    // output projection
    gemm_tf32_nt<<<dim3(HID / 128, S / 128), 256, GEMM_SMEM_BYTES>>>(CTX, Wo, out, S, HID, HID);
}

// round 6
// speedup vs baseline: 3.3460x; 1.0577x over previous
#include <cuda_runtime.h>
#include <math.h>

// ---------------- problem constants ----------------
#define S 2048
#define HID 2048
#define NH 32
#define HD 64
#define Q_W 4096            // 2*HID
#define SCALE 0.125f        // 1/sqrt(64)
#define LAM_INIT 0.7836057665316245
#define NEG_BIG (-1e30f)

// ---------------- scratch (device globals, no allocation) ----------------
__device__ float g_Q[(size_t)S * Q_W];
__device__ float g_K[(size_t)S * Q_W];
__device__ float g_V[(size_t)S * HID];
__device__ float g_O1[(size_t)S * HID];
__device__ float g_O2[(size_t)S * HID];
__device__ float g_CTX[(size_t)S * HID];
__device__ float g_cos[S * 32];
__device__ float g_sin[S * 32];
__device__ float g_lam;

// ---------------- tf32 helpers ----------------
__device__ __forceinline__ unsigned f2tf(float x) {
    unsigned r;
    asm("cvt.rna.tf32.f32 %0, %1;" : "=r"(r) : "f"(x));
    return r;
}
__device__ __forceinline__ void mma_tf32(float c[4],
                                         unsigned a0, unsigned a1, unsigned a2, unsigned a3,
                                         unsigned b0, unsigned b1) {
    asm volatile(
        "mma.sync.aligned.m16n8k8.row.col.f32.tf32.tf32.f32 "
        "{%0,%1,%2,%3},{%4,%5,%6,%7},{%8,%9},{%0,%1,%2,%3};"
        : "+f"(c[0]), "+f"(c[1]), "+f"(c[2]), "+f"(c[3])
        : "r"(a0), "r"(a1), "r"(a2), "r"(a3), "r"(b0), "r"(b1));
}

// ---------------- lambda scalar ----------------
__global__ void lam_kernel(const float* __restrict__ lq1, const float* __restrict__ lk1,
                           const float* __restrict__ lq2, const float* __restrict__ lk2) {
    if (threadIdx.x == 0) {
        float d1 = 0.f, d2 = 0.f;
        for (int i = 0; i < HD; i++) { d1 += lq1[i] * lk1[i]; d2 += lq2[i] * lk2[i]; }
        g_lam = expf(d1) - expf(d2) + (float)LAM_INIT;
    }
}

// ---------------- RoPE table (float64 like reference) ----------------
__global__ void rope_table_kernel() {
    int idx = blockIdx.x * blockDim.x + threadIdx.x;
    if (idx >= S * 32) return;
    int s = idx >> 5;
    int d = idx & 31;
    double inv = pow(10000.0, -(double)d / 32.0);
    double ang = (double)s * inv;
    g_cos[idx] = (float)cos(ang);
    g_sin[idx] = (float)sin(ang);
}

// ---------------- RoPE in-place on [S, 4096] ----------------
__global__ void rope_apply_kernel(float* __restrict__ X) {
    int idx = blockIdx.x * blockDim.x + threadIdx.x;   // S*2048 pairs
    if (idx >= S * 2048) return;
    int s    = idx >> 11;
    int p    = idx & 2047;
    int half = p >> 10;
    int rem  = p & 1023;
    int h    = rem >> 5;
    int d    = rem & 31;
    size_t base = (size_t)s * Q_W + half * HID + h * HD + d;
    float x1 = X[base];
    float x2 = X[base + 32];
    float c  = g_cos[s * 32 + d];
    float sn = g_sin[s * 32 + d];
    X[base]      = x1 * c - x2 * sn;
    X[base + 32] = x2 * c + x1 * sn;
}

// ================= TF32 GEMM: C[M,N] = A[M,K] @ B[N,K]^T =================
// block 128x128, BK=32, 8 warps (2m x 4n), warp tile 64x32 (4 x 4 mma tiles)
// Single-buffered smem, NO register staging => regs <= 128 => 2 CTAs/SM.
// Latency hiding comes from the co-resident CTA's mma phase.
#define GA_STR 36
__global__ __launch_bounds__(256, 2)
void gemm_tf32_nt(const float* __restrict__ A, const float* __restrict__ B,
                  float* __restrict__ C, int M, int N, int K) {
    __shared__ unsigned As[128 * GA_STR];
    __shared__ unsigned Bs[128 * GA_STR];
    const int tid  = threadIdx.x;
    const int lane = tid & 31;
    const int warp = tid >> 5;
    const int wm = (warp >> 2) * 64;
    const int wn = (warp & 3) * 32;
    const int bm = blockIdx.y * 128;
    const int bn = blockIdx.x * 128;
    const int a  = lane >> 2;
    const int mm = lane & 3;

    float acc[4][4][4];
#pragma unroll
    for (int i = 0; i < 4; i++)
#pragma unroll
        for (int j = 0; j < 4; j++)
#pragma unroll
            for (int r = 0; r < 4; r++) acc[i][j][r] = 0.f;

    const float* Ab = A + (size_t)bm * K;
    const float* Bb = B + (size_t)bn * K;

    for (int k0 = 0; k0 < K; k0 += 32) {
        __syncthreads();   // previous tile's mma reads complete
#pragma unroll
        for (int i = 0; i < 4; i++) {
            int lin = i * 256 + tid, row = lin >> 3, q = lin & 7;
            float4 va = *(const float4*)(Ab + (size_t)row * K + k0 + q * 4);
            float4 vb = *(const float4*)(Bb + (size_t)row * K + k0 + q * 4);
            unsigned* pa = &As[row * GA_STR + q * 4];
            pa[0] = f2tf(va.x); pa[1] = f2tf(va.y);
            pa[2] = f2tf(va.z); pa[3] = f2tf(va.w);
            unsigned* pb = &Bs[row * GA_STR + q * 4];
            pb[0] = f2tf(vb.x); pb[1] = f2tf(vb.y);
            pb[2] = f2tf(vb.z); pb[3] = f2tf(vb.w);
        }
        __syncthreads();

#pragma unroll
        for (int k8 = 0; k8 < 4; k8++) {
            unsigned af[4][4], bf[4][2];
#pragma unroll
            for (int i = 0; i < 4; i++) {
                const unsigned* p  = &As[(wm + i * 16 + a) * GA_STR + k8 * 8 + mm];
                const unsigned* p2 = p + 8 * GA_STR;
                af[i][0] = p[0];  af[i][2] = p[4];
                af[i][1] = p2[0]; af[i][3] = p2[4];
            }
#pragma unroll
            for (int j = 0; j < 4; j++) {
                const unsigned* p = &Bs[(wn + j * 8 + a) * GA_STR + k8 * 8 + mm];
                bf[j][0] = p[0]; bf[j][1] = p[4];
            }
#pragma unroll
            for (int i = 0; i < 4; i++)
#pragma unroll
                for (int j = 0; j < 4; j++)
                    mma_tf32(acc[i][j], af[i][0], af[i][1], af[i][2], af[i][3],
                             bf[j][0], bf[j][1]);
        }
    }

#pragma unroll
    for (int i = 0; i < 4; i++) {
        int row = bm + wm + i * 16 + a;
#pragma unroll
        for (int j = 0; j < 4; j++) {
            int col = bn + wn + j * 8 + mm * 2;
            *(float2*)&C[(size_t)row * N + col]       = make_float2(acc[i][j][0], acc[i][j][1]);
            *(float2*)&C[(size_t)(row + 8) * N + col] = make_float2(acc[i][j][2], acc[i][j][3]);
        }
    }
}

// ================= TF32 flash attention (both streams via blockIdx.z) ======
// q-block 128 rows, 8 warps each own m16 x full n; kv tiles of 64.
#define QS_STR 68
#define KS_STR 68
#define VS_STR 72
#define PS_STR 68
#define QS_OFF 0
#define KS_OFF (128 * QS_STR)                 // 8704
#define VS_OFF (KS_OFF + 64 * KS_STR)         // 13056
#define PS_OFF (VS_OFF + 64 * VS_STR)         // 17664
#define FLASH_WORDS (PS_OFF + 128 * PS_STR)   // 26368
#define FLASH_BYTES (FLASH_WORDS * 4)         // 105472

__global__ __launch_bounds__(256, 2)
void flash_tf32(const float* __restrict__ Qg, const float* __restrict__ Kg,
                const float* __restrict__ Vg,
                float* __restrict__ O1g, float* __restrict__ O2g) {
    extern __shared__ unsigned smw[];
    unsigned* Qs = smw + QS_OFF;
    unsigned* Ks = smw + KS_OFF;
    unsigned* Vs = smw + VS_OFF;
    unsigned* Ps = smw + PS_OFF;

    const int tid  = threadIdx.x;
    const int lane = tid & 31;
    const int warp = tid >> 5;
    const int a  = lane >> 2;
    const int mm = lane & 3;
    const int qi = gridDim.x - 1 - blockIdx.x;   // heavy tiles first
    const int h  = blockIdx.y;
    const int st = blockIdx.z;
    const int coff = st * HID + h * HD;
    float* Og = st ? O2g : O1g;
    const int r0 = qi * 128;
    const int m0 = warp * 16;
    const int rA = m0 + a;

    // load Q tile (rope already applied in gmem)
#pragma unroll
    for (int i = 0; i < 8; i++) {
        int lin = i * 256 + tid, row = lin >> 4, q = lin & 15;
        float4 v = *(const float4*)(Qg + (size_t)(r0 + row) * Q_W + coff + q * 4);
        unsigned* p = &Qs[row * QS_STR + q * 4];
        p[0] = f2tf(v.x); p[1] = f2tf(v.y); p[2] = f2tf(v.z); p[3] = f2tf(v.w);
    }

    float oacc[8][4];
#pragma unroll
    for (int j = 0; j < 8; j++)
#pragma unroll
        for (int r = 0; r < 4; r++) oacc[j][r] = 0.f;
    float mr0 = NEG_BIG, mr1 = NEG_BIG, lr0 = 0.f, lr1 = 0.f;

    const int ktmax = 2 * qi + 1;
    for (int kt = 0; kt <= ktmax; kt++) {
        int c0 = kt * 64;
        float4 rk[4], rv[4];
#pragma unroll
        for (int i = 0; i < 4; i++) {
            int lin = i * 256 + tid, row = lin >> 4, q = lin & 15;
            rk[i] = *(const float4*)(Kg + (size_t)(c0 + row) * Q_W + coff + q * 4);
            rv[i] = *(const float4*)(Vg + (size_t)(c0 + row) * HID + h * HD + q * 4);
        }
        __syncthreads();
#pragma unroll
        for (int i = 0; i < 4; i++) {
            int lin = i * 256 + tid, row = lin >> 4, q = lin & 15;
            unsigned* pk = &Ks[row * KS_STR + q * 4];
            pk[0] = f2tf(rk[i].x); pk[1] = f2tf(rk[i].y);
            pk[2] = f2tf(rk[i].z); pk[3] = f2tf(rk[i].w);
            unsigned* pv = &Vs[row * VS_STR + q * 4];
            pv[0] = f2tf(rv[i].x); pv[1] = f2tf(rv[i].y);
            pv[2] = f2tf(rv[i].z); pv[3] = f2tf(rv[i].w);
        }
        __syncthreads();

        // ---- S = Q K^T ----
        float sacc[8][4];
#pragma unroll
        for (int j = 0; j < 8; j++)
#pragma unroll
            for (int r = 0; r < 4; r++) sacc[j][r] = 0.f;

#pragma unroll
        for (int d8 = 0; d8 < 8; d8++) {
            unsigned a0 = Qs[rA * QS_STR + d8 * 8 + mm];
            unsigned a2 = Qs[rA * QS_STR + d8 * 8 + mm + 4];
            unsigned a1 = Qs[(rA + 8) * QS_STR + d8 * 8 + mm];
            unsigned a3 = Qs[(rA + 8) * QS_STR + d8 * 8 + mm + 4];
#pragma unroll
            for (int j = 0; j < 8; j++) {
                unsigned b0 = Ks[(j * 8 + a) * KS_STR + d8 * 8 + mm];
                unsigned b1 = Ks[(j * 8 + a) * KS_STR + d8 * 8 + mm + 4];
                mma_tf32(sacc[j], a0, a1, a2, a3, b0, b1);
            }
        }

        // ---- scale + causal mask ----
        bool dmask = (kt >= 2 * qi);
#pragma unroll
        for (int j = 0; j < 8; j++) {
#pragma unroll
            for (int r = 0; r < 4; r++) {
                float v = sacc[j][r] * SCALE;
                if (dmask) {
                    int gr = r0 + m0 + a + ((r >> 1) << 3);
                    int gc = c0 + j * 8 + mm * 2 + (r & 1);
                    if (gc > gr) v = NEG_BIG;
                }
                sacc[j][r] = v;
            }
        }

        // ---- online softmax (rows owned within 4-lane groups) ----
        float mx0 = NEG_BIG, mx1 = NEG_BIG;
#pragma unroll
        for (int j = 0; j < 8; j++) {
            mx0 = fmaxf(mx0, fmaxf(sacc[j][0], sacc[j][1]));
            mx1 = fmaxf(mx1, fmaxf(sacc[j][2], sacc[j][3]));
        }
        mx0 = fmaxf(mx0, __shfl_xor_sync(0xffffffffu, mx0, 1));
        mx0 = fmaxf(mx0, __shfl_xor_sync(0xffffffffu, mx0, 2));
        mx1 = fmaxf(mx1, __shfl_xor_sync(0xffffffffu, mx1, 1));
        mx1 = fmaxf(mx1, __shfl_xor_sync(0xffffffffu, mx1, 2));
        float mn0 = fmaxf(mr0, mx0), mn1 = fmaxf(mr1, mx1);
        float corr0 = __expf(mr0 - mn0), corr1 = __expf(mr1 - mn1);
        mr0 = mn0; mr1 = mn1;

        float ps0 = 0.f, ps1 = 0.f;
#pragma unroll
        for (int j = 0; j < 8; j++) {
            float p0 = __expf(sacc[j][0] - mn0);
            float p1 = __expf(sacc[j][1] - mn0);
            float p2 = __expf(sacc[j][2] - mn1);
            float p3 = __expf(sacc[j][3] - mn1);
            ps0 += p0 + p1; ps1 += p2 + p3;
            int col = j * 8 + mm * 2;
            Ps[rA * PS_STR + col]           = f2tf(p0);
            Ps[rA * PS_STR + col + 1]       = f2tf(p1);
            Ps[(rA + 8) * PS_STR + col]     = f2tf(p2);
            Ps[(rA + 8) * PS_STR + col + 1] = f2tf(p3);
        }
        ps0 += __shfl_xor_sync(0xffffffffu, ps0, 1);
        ps0 += __shfl_xor_sync(0xffffffffu, ps0, 2);
        ps1 += __shfl_xor_sync(0xffffffffu, ps1, 1);
        ps1 += __shfl_xor_sync(0xffffffffu, ps1, 2);
        lr0 = lr0 * corr0 + ps0;
        lr1 = lr1 * corr1 + ps1;
#pragma unroll
        for (int j = 0; j < 8; j++) {
            oacc[j][0] *= corr0; oacc[j][1] *= corr0;
            oacc[j][2] *= corr1; oacc[j][3] *= corr1;
        }
        __syncwarp();

        // ---- O += P V ----
#pragma unroll
        for (int kv8 = 0; kv8 < 8; kv8++) {
            unsigned a0 = Ps[rA * PS_STR + kv8 * 8 + mm];
            unsigned a2 = Ps[rA * PS_STR + kv8 * 8 + mm + 4];
            unsigned a1 = Ps[(rA + 8) * PS_STR + kv8 * 8 + mm];
            unsigned a3 = Ps[(rA + 8) * PS_STR + kv8 * 8 + mm + 4];
#pragma unroll
            for (int j = 0; j < 8; j++) {
                unsigned b0 = Vs[(kv8 * 8 + mm) * VS_STR + j * 8 + a];
                unsigned b1 = Vs[(kv8 * 8 + mm + 4) * VS_STR + j * 8 + a];
                mma_tf32(oacc[j], a0, a1, a2, a3, b0, b1);
            }
        }
    }

    // ---- epilogue: normalize + write ----
    float il0 = 1.f / lr0, il1 = 1.f / lr1;
#pragma unroll
    for (int j = 0; j < 8; j++) {
        int col = j * 8 + mm * 2;
        *(float2*)&Og[(size_t)(r0 + m0 + a) * HID + h * HD + col] =
            make_float2(oacc[j][0] * il0, oacc[j][1] * il0);
        *(float2*)&Og[(size_t)(r0 + m0 + a + 8) * HID + h * HD + col] =
            make_float2(oacc[j][2] * il1, oacc[j][3] * il1);
    }
}

// ---------------- combine: ctx = rmsnorm(o1 - lam*o2) * subln * (1-lam_init) ----
__global__ __launch_bounds__(256)
void combine_kernel(const float* __restrict__ subln, float* __restrict__ ctx) {
    int warp = blockIdx.x * 8 + (threadIdx.x >> 5);
    int lane = threadIdx.x & 31;
    if (warp >= S * NH) return;
    int s = warp >> 5;
    int h = warp & 31;
    size_t base = (size_t)s * HID + h * HD + lane;
    float lam = g_lam;
    float c0 = g_O1[base]      - lam * g_O2[base];
    float c1 = g_O1[base + 32] - lam * g_O2[base + 32];
    float ss = c0 * c0 + c1 * c1;
#pragma unroll
    for (int o = 16; o >= 1; o >>= 1)
        ss += __shfl_xor_sync(0xffffffffu, ss, o);
    float inv = rsqrtf(ss * (1.f / 64.f) + 1e-6f);
    float sc  = inv * (1.f - (float)LAM_INIT);
    ctx[base]      = c0 * sc * subln[lane];
    ctx[base + 32] = c1 * sc * subln[lane + 32];
}

// ---------------- host launcher ----------------
extern "C" void kernel_launch(void* const* d_in, const int* in_sizes, int n_in,
                              void* d_out, int out_size) {
    const float* hid  = (const float*)d_in[0];
    const float* Wq   = (const float*)d_in[1];
    const float* Wk   = (const float*)d_in[2];
    const float* Wv   = (const float*)d_in[3];
    const float* Wo   = (const float*)d_in[4];
    const float* lq1  = (const float*)d_in[5];
    const float* lk1  = (const float*)d_in[6];
    const float* lq2  = (const float*)d_in[7];
    const float* lk2  = (const float*)d_in[8];
    const float* subw = (const float*)d_in[9];
    float* out = (float*)d_out;

    float *Q, *K, *V, *O1, *O2, *CTX;
    cudaGetSymbolAddress((void**)&Q,   g_Q);
    cudaGetSymbolAddress((void**)&K,   g_K);
    cudaGetSymbolAddress((void**)&V,   g_V);
    cudaGetSymbolAddress((void**)&O1,  g_O1);
    cudaGetSymbolAddress((void**)&O2,  g_O2);
    cudaGetSymbolAddress((void**)&CTX, g_CTX);

    cudaFuncSetAttribute(flash_tf32,
                         cudaFuncAttributeMaxDynamicSharedMemorySize, FLASH_BYTES);

    // lambda + rope table
    lam_kernel<<<1, 32>>>(lq1, lk1, lq2, lk2);
    rope_table_kernel<<<(S * 32 + 255) / 256, 256>>>();

    // projections (tf32 tensor core, 2 CTAs/SM)
    gemm_tf32_nt<<<dim3(Q_W / 128, S / 128), 256>>>(hid, Wq, Q, S, Q_W, HID);
    gemm_tf32_nt<<<dim3(Q_W / 128, S / 128), 256>>>(hid, Wk, K, S, Q_W, HID);
    gemm_tf32_nt<<<dim3(HID / 128, S / 128), 256>>>(hid, Wv, V, S, HID, HID);

    // RoPE on Q and K (both halves)
    rope_apply_kernel<<<(S * 2048 + 255) / 256, 256>>>(Q);
    rope_apply_kernel<<<(S * 2048 + 255) / 256, 256>>>(K);

    // both differential-attention streams in one launch
    flash_tf32<<<dim3(S / 128, NH, 2), 256, FLASH_BYTES>>>(Q, K, V, O1, O2);

    // differential combine + headwise RMSNorm
    combine_kernel<<<(S * NH + 7) / 8, 256>>>(subw, CTX);

    // output projection
    gemm_tf32_nt<<<dim3(HID / 128, S / 128), 256>>>(CTX, Wo, out, S, HID, HID);
}